// round 16
// baseline (speedup 1.0000x reference)
#include <cuda_runtime.h>
#include <cuda_bf16.h>
#include <cstdint>

#define N_NODES 100000
#define MAX_E   1600000
#define MAX_F   200

// Scratch (allocation-free rule: __device__ globals)
__device__ float g_tmp [N_NODES * MAX_F];   // GEMM output, pre-scaled by dinv[row]
__device__ float g_bufA[N_NODES * MAX_F];   // activations ping (unpadded)
__device__ float g_bufB[N_NODES * MAX_F];   // activations pong (unpadded)
__device__ float g_dinv[N_NODES];
__device__ int   g_deg [N_NODES];
__device__ int   g_rowptr[N_NODES + 1];
__device__ int   g_cursor[N_NODES];
__device__ int   g_srcs[MAX_E];             // CSR-by-dst: source node ids
__device__ int   g_bsums[512];

// ---------------------------------------------------------------------------
// degree / CSR build (5 setup launches so launch #6 = layer-1 GEMM for ncu)
// ---------------------------------------------------------------------------
__global__ void deg_zero_kernel(int* deg, int n) {
    int i = blockIdx.x * blockDim.x + threadIdx.x;
    if (i < n) deg[i] = 0;
}

__global__ void deg_count_kernel(const int* __restrict__ dst, int* deg, int E) {
    int e = blockIdx.x * blockDim.x + threadIdx.x;
    if (e < E) atomicAdd(&deg[dst[e]], 1);
}

__global__ void blocksum_kernel(const int* __restrict__ deg, int* bsums, int n) {
    __shared__ int sh[256];
    const int i = blockIdx.x * 256 + threadIdx.x;
    sh[threadIdx.x] = (i < n) ? deg[i] : 0;
    __syncthreads();
#pragma unroll
    for (int s = 128; s > 0; s >>= 1) {
        if (threadIdx.x < s) sh[threadIdx.x] += sh[threadIdx.x + s];
        __syncthreads();
    }
    if (threadIdx.x == 0) bsums[blockIdx.x] = sh[0];
}

__global__ void scan_bsums_kernel(int* bsums, int nb, int* rowptr, int n) {
    __shared__ int sh[512];
    const int t = threadIdx.x;
    sh[t] = (t < nb) ? bsums[t] : 0;
    __syncthreads();
#pragma unroll
    for (int off = 1; off < 512; off <<= 1) {
        int u = (t >= off) ? sh[t - off] : 0;
        __syncthreads();
        sh[t] += u;
        __syncthreads();
    }
    if (t < nb) bsums[t] = (t == 0) ? 0 : sh[t - 1];
    if (t == 511) rowptr[n] = sh[511];
}

// local scan + dinv fused (keeps setup at 5 launches)
__global__ void local_scan_dinv_kernel(const int* __restrict__ deg, const int* __restrict__ boff,
                                       int* rowptr, int* cursor, float* dinv, int n) {
    __shared__ int sh[256];
    const int i = blockIdx.x * 256 + threadIdx.x;
    const int t = threadIdx.x;
    const int d = (i < n) ? deg[i] : 0;
    sh[t] = d;
    __syncthreads();
#pragma unroll
    for (int off = 1; off < 256; off <<= 1) {
        int u = (t >= off) ? sh[t - off] : 0;
        __syncthreads();
        sh[t] += u;
        __syncthreads();
    }
    if (i < n) {
        const int excl = boff[blockIdx.x] + ((t == 0) ? 0 : sh[t - 1]);
        rowptr[i] = excl;
        cursor[i] = excl;
        dinv[i] = rsqrtf((float)(d + 1));  // +1 self loop
    }
}

__global__ void fill_kernel(const int* __restrict__ src, const int* __restrict__ dst,
                            int* cursor, int* srcs, int E) {
    int e = blockIdx.x * blockDim.x + threadIdx.x;
    if (e < E) {
        int pos = atomicAdd(&cursor[dst[e]], 1);
        srcs[pos] = src[e];
    }
}

// ---------------------------------------------------------------------------
// bf16-split tensor-core GEMM + dinv pre-scale epilogue:
//   C[M,ldc] = dinv[row] * ( (relu?)A[M,K] @ W[K,N] )
//   product = Ahi*Whi + Ahi*Wlo + Alo*Whi   (lo*lo dropped, ~1e-5 rel err)
// Block tile 128(M) x 64(N), BK=32. 8 warps: 4(M) x 2(N), warp tile 32x32.
// ---------------------------------------------------------------------------
#define SMS 34   // smem k-stride (padded, even, bank-spread)

__device__ __forceinline__ void mma_bf16(float* c, const uint32_t* a, const uint32_t* b) {
    asm volatile(
        "mma.sync.aligned.m16n8k16.row.col.f32.bf16.bf16.f32 "
        "{%0,%1,%2,%3}, {%4,%5,%6,%7}, {%8,%9}, {%0,%1,%2,%3};"
        : "+f"(c[0]), "+f"(c[1]), "+f"(c[2]), "+f"(c[3])
        : "r"(a[0]), "r"(a[1]), "r"(a[2]), "r"(a[3]), "r"(b[0]), "r"(b[1]));
}

template<int DO_RELU>
__global__ __launch_bounds__(256, 2)
void gemm_bf16x2_kernel(const float* __restrict__ A, const float* __restrict__ W,
                        const float* __restrict__ dinv,
                        float* __restrict__ C, int M, int K, int N, int ldc) {
    __shared__ __align__(16) unsigned short As_hi[128 * SMS];
    __shared__ __align__(16) unsigned short As_lo[128 * SMS];
    __shared__ __align__(16) unsigned short Bs_hi[64 * SMS];
    __shared__ __align__(16) unsigned short Bs_lo[64 * SMS];

    const int tid  = threadIdx.x;
    const int warp = tid >> 5;
    const int lane = tid & 31;
    const int gid  = lane >> 2;
    const int tig  = lane & 3;
    const int wm   = warp & 3;
    const int wn   = warp >> 2;

    const int row0 = blockIdx.y * 128;
    const int col0 = blockIdx.x * 64;

    float acc[2][4][4];
#pragma unroll
    for (int mt = 0; mt < 2; mt++)
#pragma unroll
        for (int nt = 0; nt < 4; nt++)
#pragma unroll
            for (int c = 0; c < 4; c++) acc[mt][nt][c] = 0.0f;

    for (int k0 = 0; k0 < K; k0 += 32) {
#pragma unroll
        for (int i = 0; i < 16; i++) {
            const int idx = tid + i * 256;
            const int r  = idx >> 5;
            const int kk = idx & 31;
            const int gr = row0 + r;
            const int gk = k0 + kk;
            float v = 0.0f;
            if (gr < M && gk < K) v = A[(long)gr * K + gk];
            if (DO_RELU) v = fmaxf(v, 0.0f);
            __nv_bfloat16 hi = __float2bfloat16(v);
            __nv_bfloat16 lo = __float2bfloat16(v - __bfloat162float(hi));
            As_hi[r * SMS + kk] = *reinterpret_cast<unsigned short*>(&hi);
            As_lo[r * SMS + kk] = *reinterpret_cast<unsigned short*>(&lo);
        }
#pragma unroll
        for (int i = 0; i < 8; i++) {
            const int idx = tid + i * 256;
            const int kk = idx >> 6;
            const int nn = idx & 63;
            const int gk = k0 + kk;
            const int gn = col0 + nn;
            float v = 0.0f;
            if (gk < K && gn < N) v = W[(long)gk * N + gn];
            __nv_bfloat16 hi = __float2bfloat16(v);
            __nv_bfloat16 lo = __float2bfloat16(v - __bfloat162float(hi));
            Bs_hi[nn * SMS + kk] = *reinterpret_cast<unsigned short*>(&hi);
            Bs_lo[nn * SMS + kk] = *reinterpret_cast<unsigned short*>(&lo);
        }
        __syncthreads();

#pragma unroll
        for (int ks = 0; ks < 2; ks++) {
            const int kb = ks * 16;
            uint32_t a_hi[2][4], a_lo[2][4], b_hi[4][2], b_lo[4][2];
#pragma unroll
            for (int mt = 0; mt < 2; mt++) {
                const int r = wm * 32 + mt * 16 + gid;
                const int kq = kb + 2 * tig;
                a_hi[mt][0] = *(const uint32_t*)&As_hi[(r)     * SMS + kq];
                a_hi[mt][1] = *(const uint32_t*)&As_hi[(r + 8) * SMS + kq];
                a_hi[mt][2] = *(const uint32_t*)&As_hi[(r)     * SMS + kq + 8];
                a_hi[mt][3] = *(const uint32_t*)&As_hi[(r + 8) * SMS + kq + 8];
                a_lo[mt][0] = *(const uint32_t*)&As_lo[(r)     * SMS + kq];
                a_lo[mt][1] = *(const uint32_t*)&As_lo[(r + 8) * SMS + kq];
                a_lo[mt][2] = *(const uint32_t*)&As_lo[(r)     * SMS + kq + 8];
                a_lo[mt][3] = *(const uint32_t*)&As_lo[(r + 8) * SMS + kq + 8];
            }
#pragma unroll
            for (int nt = 0; nt < 4; nt++) {
                const int nr = wn * 32 + nt * 8 + gid;
                const int kq = kb + 2 * tig;
                b_hi[nt][0] = *(const uint32_t*)&Bs_hi[nr * SMS + kq];
                b_hi[nt][1] = *(const uint32_t*)&Bs_hi[nr * SMS + kq + 8];
                b_lo[nt][0] = *(const uint32_t*)&Bs_lo[nr * SMS + kq];
                b_lo[nt][1] = *(const uint32_t*)&Bs_lo[nr * SMS + kq + 8];
            }
#pragma unroll
            for (int mt = 0; mt < 2; mt++)
#pragma unroll
                for (int nt = 0; nt < 4; nt++) {
                    mma_bf16(acc[mt][nt], a_hi[mt], b_hi[nt]);
                    mma_bf16(acc[mt][nt], a_hi[mt], b_lo[nt]);
                    mma_bf16(acc[mt][nt], a_lo[mt], b_hi[nt]);
                }
        }
        __syncthreads();
    }

#pragma unroll
    for (int mt = 0; mt < 2; mt++) {
        const int r = row0 + wm * 32 + mt * 16 + gid;
        const float d0 = (r < M)     ? dinv[r]     : 0.0f;
        const float d1 = (r + 8 < M) ? dinv[r + 8] : 0.0f;
#pragma unroll
        for (int nt = 0; nt < 4; nt++) {
            const int cc = col0 + wn * 32 + nt * 8 + 2 * tig;
            if (cc < ldc) {
                if (r < M) {
                    float2 v = make_float2(d0 * acc[mt][nt][0], d0 * acc[mt][nt][1]);
                    *(float2*)&C[(long)r * ldc + cc] = v;
                }
                if (r + 8 < M) {
                    float2 v = make_float2(d1 * acc[mt][nt][2], d1 * acc[mt][nt][3]);
                    *(float2*)&C[(long)(r + 8) * ldc + cc] = v;
                }
            }
        }
    }
}

// ---------------------------------------------------------------------------
// gather: one warp per node; 8-edge unroll; pre-scaled rows.
//   out[i][f] = dinv[i]*( S[i][f] + sum_e S[src][f] ) + b[f]
// ---------------------------------------------------------------------------
template<int NR>
__global__ __launch_bounds__(256)
void gather4_kernel(const float* __restrict__ t,
                    const int* __restrict__ rowptr,
                    const int* __restrict__ srcs,
                    const float* __restrict__ dinv,
                    const float* __restrict__ bias,
                    float* __restrict__ out, int n, int F, int ldc) {
    const int warp = (blockIdx.x * blockDim.x + threadIdx.x) >> 5;
    const int lane = threadIdx.x & 31;
    if (warp >= n) return;
    const int i = warp;
    const int nq = ldc >> 2;

    float4 sums[NR];
    {
        const float4* trow = (const float4*)(t + (long)i * ldc);
#pragma unroll
        for (int r = 0; r < NR; r++) {
            const int q = lane + r * 32;
            sums[r] = (q < nq) ? trow[q] : make_float4(0.f, 0.f, 0.f, 0.f);
        }
    }

    const int e0 = rowptr[i];
    const int e1 = rowptr[i + 1];
    int e = e0;
    for (; e + 7 < e1; e += 8) {
        const float4* rp[8];
#pragma unroll
        for (int j = 0; j < 8; j++)
            rp[j] = (const float4*)(t + (long)srcs[e + j] * ldc);
#pragma unroll
        for (int r = 0; r < NR; r++) {
            const int q = lane + r * 32;
            if (q < nq) {
                float4 v0 = rp[0][q], v1 = rp[1][q], v2 = rp[2][q], v3 = rp[3][q];
                float4 v4 = rp[4][q], v5 = rp[5][q], v6 = rp[6][q], v7 = rp[7][q];
                sums[r].x += (v0.x + v1.x) + (v2.x + v3.x) + (v4.x + v5.x) + (v6.x + v7.x);
                sums[r].y += (v0.y + v1.y) + (v2.y + v3.y) + (v4.y + v5.y) + (v6.y + v7.y);
                sums[r].z += (v0.z + v1.z) + (v2.z + v3.z) + (v4.z + v5.z) + (v6.z + v7.z);
                sums[r].w += (v0.w + v1.w) + (v2.w + v3.w) + (v4.w + v5.w) + (v6.w + v7.w);
            }
        }
    }
    for (; e + 3 < e1; e += 4) {
        const float4* rp[4];
#pragma unroll
        for (int j = 0; j < 4; j++)
            rp[j] = (const float4*)(t + (long)srcs[e + j] * ldc);
#pragma unroll
        for (int r = 0; r < NR; r++) {
            const int q = lane + r * 32;
            if (q < nq) {
                float4 v0 = rp[0][q], v1 = rp[1][q], v2 = rp[2][q], v3 = rp[3][q];
                sums[r].x += (v0.x + v1.x) + (v2.x + v3.x);
                sums[r].y += (v0.y + v1.y) + (v2.y + v3.y);
                sums[r].z += (v0.z + v1.z) + (v2.z + v3.z);
                sums[r].w += (v0.w + v1.w) + (v2.w + v3.w);
            }
        }
    }
    for (; e < e1; e++) {
        const float4* r0 = (const float4*)(t + (long)srcs[e] * ldc);
#pragma unroll
        for (int r = 0; r < NR; r++) {
            const int q = lane + r * 32;
            if (q < nq) {
                float4 v0 = r0[q];
                sums[r].x += v0.x;
                sums[r].y += v0.y;
                sums[r].z += v0.z;
                sums[r].w += v0.w;
            }
        }
    }

    const float di = dinv[i];
    float* orow = out + (long)i * F;
#pragma unroll
    for (int r = 0; r < NR; r++) {
        const int q = lane + r * 32;
        if (q < nq) {
            const int f = q * 4;
            const float s4[4] = { sums[r].x, sums[r].y, sums[r].z, sums[r].w };
#pragma unroll
            for (int c = 0; c < 4; c++) {
                const int ff = f + c;
                if (ff < F) orow[ff] = fmaf(di, s4[c], bias[ff]);
            }
        }
    }
}

// ---------------------------------------------------------------------------
// host
// ---------------------------------------------------------------------------
static void launch_gather(const float* t, const int* rowptr, const int* srcs,
                          const float* dinv, const float* bias, float* out,
                          int n, int F, int ldc) {
    const int blocks = (n + 7) / 8;
    const int nq = ldc / 4;
    if (nq > 32)
        gather4_kernel<2><<<blocks, 256>>>(t, rowptr, srcs, dinv, bias, out, n, F, ldc);
    else
        gather4_kernel<1><<<blocks, 256>>>(t, rowptr, srcs, dinv, bias, out, n, F, ldc);
}

extern "C" void kernel_launch(void* const* d_in, const int* in_sizes, int n_in,
                              void* d_out, int out_size) {
    const float* x   = (const float*)d_in[0];
    const int* eidx  = (const int*)d_in[1];
    const int E      = in_sizes[1] / 2;
    const int* srcp  = eidx;
    const int* dstp  = eidx + E;

    const float* W[5] = { (const float*)d_in[2], (const float*)d_in[4],
                          (const float*)d_in[6], (const float*)d_in[8],
                          (const float*)d_in[10] };
    const float* B[5] = { (const float*)d_in[3], (const float*)d_in[5],
                          (const float*)d_in[7], (const float*)d_in[9],
                          (const float*)d_in[11] };
    const int dims[6] = {512, 200, 175, 125, 75, 50};
    const int N = N_NODES;

    float *tmp, *bufA, *bufB, *dinv;
    int *deg, *rowptr, *cursor, *srcs, *bsums;
    cudaGetSymbolAddress((void**)&tmp,    g_tmp);
    cudaGetSymbolAddress((void**)&bufA,   g_bufA);
    cudaGetSymbolAddress((void**)&bufB,   g_bufB);
    cudaGetSymbolAddress((void**)&dinv,   g_dinv);
    cudaGetSymbolAddress((void**)&deg,    g_deg);
    cudaGetSymbolAddress((void**)&rowptr, g_rowptr);
    cudaGetSymbolAddress((void**)&cursor, g_cursor);
    cudaGetSymbolAddress((void**)&srcs,   g_srcs);
    cudaGetSymbolAddress((void**)&bsums,  g_bsums);

    const int nb = (N + 255) / 256;  // 391

    // 5 setup launches, so launch #6 (ncu's -s 5 -c 1 target) is the L1 GEMM
    deg_zero_kernel<<<(N + 255) / 256, 256>>>(deg, N);
    deg_count_kernel<<<(E + 255) / 256, 256>>>(dstp, deg, E);
    blocksum_kernel<<<nb, 256>>>(deg, bsums, N);
    scan_bsums_kernel<<<1, 512>>>(bsums, nb, rowptr, N);
    local_scan_dinv_kernel<<<nb, 256>>>(deg, bsums, rowptr, cursor, dinv, N);

    const float* in_act = x;
    float* outs[5] = { bufA, bufB, bufA, bufB, (float*)d_out };

    for (int L = 0; L < 5; L++) {
        const int Fin = dims[L], Fout = dims[L + 1];
        const int ldc = (Fout + 3) & ~3;
        dim3 ggrid((ldc + 63) / 64, (N + 127) / 128);
        if (L == 0)
            gemm_bf16x2_kernel<0><<<ggrid, 256>>>(in_act, W[L], dinv, tmp, N, Fin, Fout, ldc);
        else
            gemm_bf16x2_kernel<1><<<ggrid, 256>>>(in_act, W[L], dinv, tmp, N, Fin, Fout, ldc);

        if (L == 0) {
            // CSR fill deferred past the L1 GEMM (gather needs it; GEMM doesn't).
            fill_kernel<<<(E + 255) / 256, 256>>>(srcp, dstp, cursor, srcs, E);
        }

        launch_gather(tmp, rowptr, srcs, dinv, B[L], outs[L], N, Fout, ldc);
        in_act = outs[L];
    }
}